// round 7
// baseline (speedup 1.0000x reference)
#include <cuda_runtime.h>
#include <math.h>

typedef unsigned long long ull;

// SpatialGRU B=64,C=16,L=R=64,U=64,K=208. Persistent row-pipelined kernel.
// Round-7: H ring kept in m-paired [u][mp] float2 layout => GEMM1 reads the
// ring directly (segment table over permuted-K weights); reduce1 writes A2
// directly (rr*H); W2 resident in smem; x columns pre-paired in global.

#define KDIM 208
#define N1   384
#define JT   6

// smem float offsets
#define P_OFF    0          // [4 kg][6 j][8 mp][64 nl] float2 = 24576 floats
#define W2S_OFF  24576      // 208*64 = 13312
#define AS2_OFF  37888      // [192][8] float2 = 3072
#define HE_OFF   40960      // [2][64][8] float2 = 2048
#define HO_OFF   43008      // 2048
#define HT_OFF   45056      // 2048
#define XS_OFF   47104      // [16][8] float2 = 256
#define YP_OFF   47360      // [3][64][8] float2 = 3072
#define B1_OFF   50432      // 384
#define WIJB_OFF 50816      // 64
#define SMEM_FLOATS 50880
#define SMEM_BYTES (SMEM_FLOATS*4)

__device__ float  g_H[64 * 64 * 64 * 64];  // [(l*64+r)][q*1024], inside: [u][mp] float2
__device__ float2 g_Xp[4096 * 4 * 128];    // [(l*64+r)][q][c][mp] pairs
__device__ float  g_Wt1[208 * 384];        // permuted k rows; n<192 wr, n>=192 wz-diff
__device__ float  g_Wt2[208 * 64];         // [k][n] k<192: U_w ; else wij
__device__ int    g_flag[4 * 64 * 64];     // [q][row][r]

#define FMA2(acc, a, b) asm("fma.rn.f32x2 %0, %1, %2, %0;" : "+l"(acc) : "l"(a), "l"(b))

__device__ __forceinline__ ull dup2(float w) {
    unsigned int wi = __float_as_uint(w);
    ull d;
    asm("mov.b64 %0, {%1,%2};" : "=l"(d) : "r"(wi), "r"(wi));
    return d;
}
__device__ __forceinline__ float2 unpack2(ull v) {
    unsigned int a, b;
    asm("mov.b64 {%0,%1}, %2;" : "=r"(a), "=r"(b) : "l"(v));
    return make_float2(__uint_as_float(a), __uint_as_float(b));
}
__device__ __forceinline__ float fast_tanh(float x) {
    x = fminf(fmaxf(x, -15.0f), 15.0f);
    float e = __expf(2.0f * x);
    return __fdividef(e - 1.0f, e + 1.0f);
}

extern "C" __global__ void init_kernel(const float* __restrict__ inputs,
                                       const float* __restrict__ wr_w,
                                       const float* __restrict__ wz_w,
                                       const float* __restrict__ U_w,
                                       const float* __restrict__ wij_w)
{
    int t = blockIdx.x * blockDim.x + threadIdx.x;
    int stride = gridDim.x * blockDim.x;
    for (int i = t; i < 4 * 64 * 64; i += stride) g_flag[i] = 0;
    for (int i = t; i < 4096 * 4 * 128; i += stride) {
        int mp = i & 7, c = (i >> 3) & 15, q = (i >> 7) & 3, cell = i >> 9;
        int l = cell >> 6, r = cell & 63, b = q * 16 + 2 * mp;
        float v0 = inputs[((b * 16 + c) * 64 + l) * 64 + r];
        float v1 = inputs[(((b + 1) * 16 + c) * 64 + l) * 64 + r];
        g_Xp[i] = make_float2(v0, v1);
    }
    // W1: permuted k order for clean per-group segments:
    // v: [0,52)=top0-51 [52,104)=left0-51 [104,156)=diag0-51
    //    [156,168)=top52-63 [168,180)=left52-63 [180,192)=diag52-63 [192,208)=x
    for (int i = t; i < 208 * 384; i += stride) {
        int v = i / 384, n = i - v * 384;
        int ok;
        if (v < 52)       ok = v;
        else if (v < 104) ok = 64 + (v - 52);
        else if (v < 156) ok = 128 + (v - 104);
        else if (v < 168) ok = 52 + (v - 156);
        else if (v < 180) ok = 116 + (v - 168);
        else              ok = v;   // diag tail (identity) and x
        float w;
        if (n < 192) w = wr_w[n * KDIM + ok];
        else { int tt = n - 192, g = tt >> 6, u = tt & 63;
               w = wz_w[(64 * (g + 1) + u) * KDIM + ok] - wz_w[u * KDIM + ok]; }
        g_Wt1[i] = w;
    }
    for (int i = t; i < 208 * 64; i += stride) {
        int k = i >> 6, n = i & 63;
        g_Wt2[i] = (k < 192) ? U_w[n * 192 + k] : wij_w[n * 16 + (k - 192)];
    }
}

extern __shared__ float smem[];

#define SEG1(APTR, LEN, KV0) { \
    const ulonglong2* Ab_ = (const ulonglong2*)(APTR); \
    ulonglong2 aC0 = Ab_[0], aC1 = Ab_[1], aC2 = Ab_[2], aC3 = Ab_[3]; \
    _Pragma("unroll 4") \
    for (int kk = 0; kk < (LEN); kk++) { \
        ulonglong2 aN0, aN1, aN2, aN3; \
        if (kk + 1 < (LEN)) { const ulonglong2* r_ = Ab_ + (kk + 1) * 4; \
            aN0 = r_[0]; aN1 = r_[1]; aN2 = r_[2]; aN3 = r_[3]; } \
        ull wd_[JT]; \
        _Pragma("unroll") for (int j = 0; j < JT; j++) wd_[j] = dup2(wbuf[kk & 3][j]); \
        if ((KV0) + kk + 4 < 52) { \
            _Pragma("unroll") for (int j = 0; j < JT; j++) \
                wbuf[kk & 3][j] = Wb[(size_t)((KV0) + kk + 4) * N1 + 64 * j]; } \
        _Pragma("unroll") for (int j = 0; j < JT; j++) { \
            FMA2(acc[j][0], aC0.x, wd_[j]); FMA2(acc[j][1], aC0.y, wd_[j]); \
            FMA2(acc[j][2], aC1.x, wd_[j]); FMA2(acc[j][3], aC1.y, wd_[j]); \
            FMA2(acc[j][4], aC2.x, wd_[j]); FMA2(acc[j][5], aC2.y, wd_[j]); \
            FMA2(acc[j][6], aC3.x, wd_[j]); FMA2(acc[j][7], aC3.y, wd_[j]); } \
        aC0 = aN0; aC1 = aN1; aC2 = aN2; aC3 = aN3; } }

#define SEG2(APTR, LEN, KV0) { \
    const ulonglong2* Ab_ = (const ulonglong2*)(APTR); \
    ulonglong2 aC0 = Ab_[0], aC1 = Ab_[1], aC2 = Ab_[2], aC3 = Ab_[3]; \
    _Pragma("unroll 4") \
    for (int kk = 0; kk < (LEN); kk++) { \
        ulonglong2 aN0, aN1, aN2, aN3; \
        if (kk + 1 < (LEN)) { const ulonglong2* r_ = Ab_ + (kk + 1) * 4; \
            aN0 = r_[0]; aN1 = r_[1]; aN2 = r_[2]; aN3 = r_[3]; } \
        ull wd_ = dup2(w2buf[kk & 3]); \
        if ((KV0) + kk + 4 < 52) w2buf[kk & 3] = Wb2[((KV0) + kk + 4) * 64]; \
        FMA2(acc2[0], aC0.x, wd_); FMA2(acc2[1], aC0.y, wd_); \
        FMA2(acc2[2], aC1.x, wd_); FMA2(acc2[3], aC1.y, wd_); \
        FMA2(acc2[4], aC2.x, wd_); FMA2(acc2[5], aC2.y, wd_); \
        FMA2(acc2[6], aC3.x, wd_); FMA2(acc2[7], aC3.y, wd_); \
        aC0 = aN0; aC1 = aN1; aC2 = aN2; aC3 = aN3; } }

extern "C" __global__ void __launch_bounds__(256)
pipeline_kernel(const float* __restrict__ wr_b, const float* __restrict__ wz_b,
                const float* __restrict__ wij_b, float* __restrict__ out)
{
    const int tid = threadIdx.x;
    const int p = blockIdx.x >> 2;
    const int q = blockIdx.x & 3;
    const int b0 = q * 16;
    const int nl = tid & 63;           // n-lane
    const int kg = tid >> 6;           // k-group

    float2* Pv   = (float2*)(smem + P_OFF);
    float*  ws2  = smem + W2S_OFF;
    float2* As2  = (float2*)(smem + AS2_OFF);
    float2* Xs   = (float2*)(smem + XS_OFF);
    float2* Yp   = (float2*)(smem + YP_OFF);
    float*  bias1 = smem + B1_OFF;
    float*  wijb  = smem + WIJB_OFF;

    // one-time preload
    for (int i = tid; i < 208 * 64; i += 256) ws2[i] = g_Wt2[i];
    for (int i = tid; i < 384; i += 256) {
        float b;
        if (i < 192) b = wr_b[i];
        else { int tt = i - 192, g = tt >> 6, u = tt & 63;
               b = wz_b[64 * (g + 1) + u] - wz_b[u]; }
        bias1[i] = b;
    }
    if (tid < 64) wijb[tid] = wij_b[tid];
    for (int i = tid; i < 6144; i += 256) smem[HE_OFF + i] = 0.0f;  // He,Ho,Ht
    {   // Xs for s=0: cell (l=2p, r=0)
        const float2* Xp0 = g_Xp + ((size_t)((2 * p) * 64 + 0) * 4 + q) * 128;
        if (tid < 128) Xs[tid] = Xp0[tid];
    }
    __syncthreads();

    const float* Wb  = g_Wt1 + (size_t)(kg * 52) * N1 + nl;
    const float* Wb2 = ws2 + (size_t)(kg * 52) * 64 + nl;

    for (int s = 0; s < 128; s++) {
        const int sub = s & 1;
        const int r = s >> 1;
        const int l = 2 * p + sub;
        const int rb = r & 1, rp = rb ^ 1;

        float2 *T, *Lf, *Dg, *hdst;
        if (sub == 0) {
            T  = (float2*)(smem + HT_OFF) + rb * 512;
            Lf = (float2*)(smem + HE_OFF) + rp * 512;
            Dg = (float2*)(smem + HT_OFF) + rp * 512;
            hdst = (float2*)(smem + HE_OFF) + rb * 512;
        } else {
            T  = (float2*)(smem + HE_OFF) + rb * 512;
            Lf = (float2*)(smem + HO_OFF) + rp * 512;
            Dg = (float2*)(smem + HE_OFF) + rp * 512;
            hdst = (float2*)(smem + HO_OFF) + rb * 512;
        }

        if (sub == 0 && p > 0) {
            // all threads spin (acquire), then fetch top row (paired layout)
            const int* fp = &g_flag[(q * 64 + (2 * p - 1)) * 64 + r];
            int v;
            do {
                asm volatile("ld.acquire.gpu.global.b32 %0, [%1];" : "=r"(v) : "l"(fp));
                if (!v) __nanosleep(64);
            } while (!v);
            const float2* Gt = (const float2*)(g_H + ((size_t)((2 * p - 1) * 64 + r)) * 4096 + q * 1024);
            T[tid] = Gt[tid];
            T[tid + 256] = Gt[tid + 256];
            __syncthreads();
        }

        // ---- stage-1 GEMM: A read directly from H ring + Xs via segment table ----
        float wbuf[4][JT];
#pragma unroll
        for (int t4 = 0; t4 < 4; t4++)
#pragma unroll
            for (int j = 0; j < JT; j++) wbuf[t4][j] = Wb[(size_t)t4 * N1 + 64 * j];

        ull acc[JT][8];
#pragma unroll
        for (int j = 0; j < JT; j++)
#pragma unroll
            for (int m = 0; m < 8; m++) acc[j][m] = 0ULL;

        if (kg == 0)      { SEG1(T,  52, 0) }
        else if (kg == 1) { SEG1(Lf, 52, 0) }
        else if (kg == 2) { SEG1(Dg, 52, 0) }
        else {
            SEG1(T + 416,  12, 0)
            SEG1(Lf + 416, 12, 12)
            SEG1(Dg + 416, 12, 24)
            SEG1(Xs,       16, 36)
        }
#pragma unroll
        for (int j = 0; j < JT; j++)
#pragma unroll
            for (int m = 0; m < 8; m++)
                Pv[(size_t)kg * 3072 + (j * 8 + m) * 64 + nl] = unpack2(acc[j][m]);
        __syncthreads();

        // ---- reduce1: rr -> As2 (rr * H, paired), z-diff -> Yp ----
#pragma unroll
        for (int i = 0; i < 12; i++) {
            int f = tid + 256 * i;
            int nl2 = f & 63, rest = f >> 6;
            int m = rest & 7, j = rest >> 3;
            int base = (j * 8 + m) * 64 + nl2;
            float2 s0 = Pv[base], s1 = Pv[3072 + base];
            float2 s2 = Pv[6144 + base], s3 = Pv[9216 + base];
            int n = nl2 + 64 * j;
            float b = bias1[n];
            float x0 = ((s0.x + s1.x) + (s2.x + s3.x)) + b;
            float x1 = ((s0.y + s1.y) + (s2.y + s3.y)) + b;
            if (j < 3) {
                x0 = __fdividef(1.0f, 1.0f + __expf(-x0));
                x1 = __fdividef(1.0f, 1.0f + __expf(-x1));
                const float2* hsrc = (j == 0) ? Lf : ((j == 1) ? T : Dg);  // A2: left,top,diag
                float2 hp = hsrc[nl2 * 8 + m];
                As2[(size_t)n * 8 + m] = make_float2(x0 * hp.x, x1 * hp.y);
            } else {
                Yp[(size_t)(j - 3) * 512 + nl2 * 8 + m] = make_float2(x0, x1);
            }
        }
        __syncthreads();

        // ---- stage-2 GEMM: A = As2 (+Xs tail), W2 from smem ----
        float w2buf[4];
#pragma unroll
        for (int t4 = 0; t4 < 4; t4++) w2buf[t4] = Wb2[t4 * 64];
        ull acc2[8];
#pragma unroll
        for (int m = 0; m < 8; m++) acc2[m] = 0ULL;

        if (kg < 3) { SEG2(As2 + kg * 416, 52, 0) }
        else {
            SEG2(As2 + 1248, 36, 0)
            SEG2(Xs,         16, 36)
        }
#pragma unroll
        for (int m = 0; m < 8; m++)
            Pv[(size_t)kg * 512 + m * 64 + nl] = unpack2(acc2[m]);
        __syncthreads();

        // ---- epilogue: reduce + tanh + gates + H update (+ Xs copy for next) ----
        {
            float2* Gd = (float2*)(g_H + ((size_t)(l * 64 + r)) * 4096 + q * 1024);
            const bool last = (l == 63) && (r == 63);
#pragma unroll
            for (int i = 0; i < 2; i++) {
                int f = tid + 256 * i;
                int u = f & 63, m = f >> 6;
                int base = m * 64 + u;
                float2 s0 = Pv[base], s1 = Pv[512 + base];
                float2 s2 = Pv[1024 + base], s3 = Pv[1536 + base];
                float wb = wijb[u];
                float a0 = ((s0.x + s1.x) + (s2.x + s3.x)) + wb;
                float a1 = ((s0.y + s1.y) + (s2.y + s3.y)) + wb;
                float hn0 = fast_tanh(a0), hn1 = fast_tanh(a1);
                int pi = u * 8 + m;
                float2 z1 = Yp[pi], z2 = Yp[512 + pi], z3 = Yp[1024 + pi];
                float2 hl = Lf[pi], ht = T[pi], hd = Dg[pi];
                // component 0
                float mx0 = fmaxf(fmaxf(z1.x, z2.x), fmaxf(z3.x, 0.0f));
                float e00 = __expf(-mx0);
                float e10 = __expf(z1.x - mx0), e20 = __expf(z2.x - mx0), e30 = __expf(z3.x - mx0);
                float h0 = (e00 * hn0 + e10 * hl.x + e20 * ht.x + e30 * hd.x) *
                           __fdividef(1.0f, e00 + e10 + e20 + e30);
                // component 1
                float mx1 = fmaxf(fmaxf(z1.y, z2.y), fmaxf(z3.y, 0.0f));
                float e01 = __expf(-mx1);
                float e11 = __expf(z1.y - mx1), e21 = __expf(z2.y - mx1), e31 = __expf(z3.y - mx1);
                float h1 = (e01 * hn1 + e11 * hl.y + e21 * ht.y + e31 * hd.y) *
                           __fdividef(1.0f, e01 + e11 + e21 + e31);
                float2 h2 = make_float2(h0, h1);
                hdst[pi] = h2;
                if (sub == 1) Gd[pi] = h2;
                if (last) { out[(b0 + 2 * m) * 64 + u] = h0; out[(b0 + 2 * m + 1) * 64 + u] = h1; }
            }
            if (s < 127 && tid < 128) {   // Xs for next cell
                int s2_ = s + 1;
                int r2 = s2_ >> 1, l2 = 2 * p + (s2_ & 1);
                const float2* Xpn = g_Xp + ((size_t)(l2 * 64 + r2) * 4 + q) * 128;
                Xs[tid] = Xpn[tid];
            }
        }
        __syncthreads();

        if (sub == 1 && tid == 0) {
            __threadfence();
            int* fp = &g_flag[(q * 64 + l) * 64 + r];
            asm volatile("st.release.gpu.global.b32 [%0], %1;" :: "l"(fp), "r"(1) : "memory");
        }
    }
}

extern "C" void kernel_launch(void* const* d_in, const int* in_sizes, int n_in,
                              void* d_out, int out_size)
{
    const float* inputs = (const float*)d_in[0];
    const float* wr_w   = (const float*)d_in[1];
    const float* wr_b   = (const float*)d_in[2];
    const float* wz_w   = (const float*)d_in[3];
    const float* wz_b   = (const float*)d_in[4];
    const float* wij_w  = (const float*)d_in[5];
    const float* wij_b  = (const float*)d_in[6];
    const float* U_w    = (const float*)d_in[7];
    float* out = (float*)d_out;

    cudaFuncSetAttribute(pipeline_kernel, cudaFuncAttributeMaxDynamicSharedMemorySize, SMEM_BYTES);

    init_kernel<<<512, 256>>>(inputs, wr_w, wz_w, U_w, wij_w);
    pipeline_kernel<<<128, 256, SMEM_BYTES>>>(wr_b, wz_b, wij_b, out);
}

// round 8
// speedup vs baseline: 1.0859x; 1.0859x over previous
#include <cuda_runtime.h>
#include <math.h>

typedef unsigned long long ull;

// SpatialGRU B=64,C=16,L=R=64,U=64,K=208. Persistent row-pipelined kernel.
// Round-8: R7 fusion (ring-as-A, fused reduce1->A2, W2 in smem) with padded
// m-paired rows (stride 10 float2 = 80B: aligned LDS.128 broadcasts, 4-way
// instead of 16-way conflicts on lane-varying row accesses), tid0 spin.

#define KDIM 208
#define N1   384
#define JT   6
#define RS   10          // row stride in float2
#define RSF  20          // row stride in floats

// smem float offsets
#define P_OFF    0          // [4 kg][6 j][8 mp][64 nl] float2 = 24576 floats
#define W2S_OFF  24576      // 208*64 = 13312
#define AS2_OFF  37888      // [192][RS] float2 = 3840
#define HE_OFF   41728      // [2][64][RS] float2 = 2560
#define HO_OFF   44288      // 2560
#define HT_OFF   46848      // 2560
#define XS_OFF   49408      // [16][RS] float2 = 320
#define YP_OFF   49728      // [3][64][RS] float2 = 3840
#define B1_OFF   53568      // 384
#define WIJB_OFF 53952      // 64
#define SMEM_FLOATS 54016
#define SMEM_BYTES (SMEM_FLOATS*4)

__device__ float  g_H[64 * 64 * 64 * 64];  // [(l*64+r)][q*1024] packed [u][mp] float2
__device__ float2 g_Xp[4096 * 4 * 128];    // [(l*64+r)][q][c][mp]
__device__ float  g_Wt1[208 * 384];        // permuted-k rows; n<192 wr, n>=192 wz-diff
__device__ float  g_Wt2[208 * 64];         // [k][n] k<192: U_w ; else wij
__device__ int    g_flag[4 * 64 * 64];     // [q][row][r]

#define FMA2(acc, a, b) asm("fma.rn.f32x2 %0, %1, %2, %0;" : "+l"(acc) : "l"(a), "l"(b))

__device__ __forceinline__ ull dup2(float w) {
    unsigned int wi = __float_as_uint(w);
    ull d;
    asm("mov.b64 %0, {%1,%2};" : "=l"(d) : "r"(wi), "r"(wi));
    return d;
}
__device__ __forceinline__ float2 unpack2(ull v) {
    unsigned int a, b;
    asm("mov.b64 {%0,%1}, %2;" : "=r"(a), "=r"(b) : "l"(v));
    return make_float2(__uint_as_float(a), __uint_as_float(b));
}
__device__ __forceinline__ float fast_tanh(float x) {
    x = fminf(fmaxf(x, -15.0f), 15.0f);
    float e = __expf(2.0f * x);
    return __fdividef(e - 1.0f, e + 1.0f);
}

extern "C" __global__ void init_kernel(const float* __restrict__ inputs,
                                       const float* __restrict__ wr_w,
                                       const float* __restrict__ wz_w,
                                       const float* __restrict__ U_w,
                                       const float* __restrict__ wij_w)
{
    int t = blockIdx.x * blockDim.x + threadIdx.x;
    int stride = gridDim.x * blockDim.x;
    for (int i = t; i < 4 * 64 * 64; i += stride) g_flag[i] = 0;
    for (int i = t; i < 4096 * 4 * 128; i += stride) {
        int mp = i & 7, c = (i >> 3) & 15, q = (i >> 7) & 3, cell = i >> 9;
        int l = cell >> 6, r = cell & 63, b = q * 16 + 2 * mp;
        float v0 = inputs[((b * 16 + c) * 64 + l) * 64 + r];
        float v1 = inputs[(((b + 1) * 16 + c) * 64 + l) * 64 + r];
        g_Xp[i] = make_float2(v0, v1);
    }
    // W1 permuted k (virtual v): [0,52)=top0-51 [52,104)=left0-51 [104,156)=diag0-51
    // [156,168)=top52-63 [168,180)=left52-63 [180,192)=diag52-63(identity) [192,208)=x
    for (int i = t; i < 208 * 384; i += stride) {
        int v = i / 384, n = i - v * 384;
        int ok;
        if (v < 52)       ok = v;
        else if (v < 104) ok = 64 + (v - 52);
        else if (v < 156) ok = 128 + (v - 104);
        else if (v < 168) ok = 52 + (v - 156);
        else if (v < 180) ok = 116 + (v - 168);
        else              ok = v;
        float w;
        if (n < 192) w = wr_w[n * KDIM + ok];
        else { int tt = n - 192, g = tt >> 6, u = tt & 63;
               w = wz_w[(64 * (g + 1) + u) * KDIM + ok] - wz_w[u * KDIM + ok]; }
        g_Wt1[i] = w;
    }
    for (int i = t; i < 208 * 64; i += stride) {
        int k = i >> 6, n = i & 63;
        g_Wt2[i] = (k < 192) ? U_w[n * 192 + k] : wij_w[n * 16 + (k - 192)];
    }
}

extern __shared__ float smem[];

// stage-1 segment: rows at APTR (stride RS float2 = 5 ulonglong2), LEN rows,
// virtual-k offset KV0 within this kg's 52; W prefetch 4 deep from L2.
#define SEG1(APTR, LEN, KV0) { \
    const ulonglong2* Ab_ = (const ulonglong2*)(APTR); \
    ulonglong2 aC0 = Ab_[0], aC1 = Ab_[1], aC2 = Ab_[2], aC3 = Ab_[3]; \
    _Pragma("unroll 4") \
    for (int kk = 0; kk < (LEN); kk++) { \
        ulonglong2 aN0, aN1, aN2, aN3; \
        if (kk + 1 < (LEN)) { const ulonglong2* r_ = Ab_ + (kk + 1) * 5; \
            aN0 = r_[0]; aN1 = r_[1]; aN2 = r_[2]; aN3 = r_[3]; } \
        ull wd_[JT]; \
        _Pragma("unroll") for (int j = 0; j < JT; j++) wd_[j] = dup2(wbuf[kk & 3][j]); \
        if ((KV0) + kk + 4 < 52) { \
            _Pragma("unroll") for (int j = 0; j < JT; j++) \
                wbuf[kk & 3][j] = Wb[(size_t)((KV0) + kk + 4) * N1 + 64 * j]; } \
        _Pragma("unroll") for (int j = 0; j < JT; j++) { \
            FMA2(acc[j][0], aC0.x, wd_[j]); FMA2(acc[j][1], aC0.y, wd_[j]); \
            FMA2(acc[j][2], aC1.x, wd_[j]); FMA2(acc[j][3], aC1.y, wd_[j]); \
            FMA2(acc[j][4], aC2.x, wd_[j]); FMA2(acc[j][5], aC2.y, wd_[j]); \
            FMA2(acc[j][6], aC3.x, wd_[j]); FMA2(acc[j][7], aC3.y, wd_[j]); } \
        aC0 = aN0; aC1 = aN1; aC2 = aN2; aC3 = aN3; } }

#define SEG2(APTR, LEN, KV0) { \
    const ulonglong2* Ab_ = (const ulonglong2*)(APTR); \
    ulonglong2 aC0 = Ab_[0], aC1 = Ab_[1], aC2 = Ab_[2], aC3 = Ab_[3]; \
    _Pragma("unroll 4") \
    for (int kk = 0; kk < (LEN); kk++) { \
        ulonglong2 aN0, aN1, aN2, aN3; \
        if (kk + 1 < (LEN)) { const ulonglong2* r_ = Ab_ + (kk + 1) * 5; \
            aN0 = r_[0]; aN1 = r_[1]; aN2 = r_[2]; aN3 = r_[3]; } \
        ull wd_ = dup2(w2buf[kk & 3]); \
        if ((KV0) + kk + 4 < 52) w2buf[kk & 3] = Wb2[((KV0) + kk + 4) * 64]; \
        FMA2(acc2[0], aC0.x, wd_); FMA2(acc2[1], aC0.y, wd_); \
        FMA2(acc2[2], aC1.x, wd_); FMA2(acc2[3], aC1.y, wd_); \
        FMA2(acc2[4], aC2.x, wd_); FMA2(acc2[5], aC2.y, wd_); \
        FMA2(acc2[6], aC3.x, wd_); FMA2(acc2[7], aC3.y, wd_); \
        aC0 = aN0; aC1 = aN1; aC2 = aN2; aC3 = aN3; } }

extern "C" __global__ void __launch_bounds__(256)
pipeline_kernel(const float* __restrict__ wr_b, const float* __restrict__ wz_b,
                const float* __restrict__ wij_b, float* __restrict__ out)
{
    const int tid = threadIdx.x;
    const int p = blockIdx.x >> 2;
    const int q = blockIdx.x & 3;
    const int b0 = q * 16;
    const int nl = tid & 63;
    const int kg = tid >> 6;

    float2* Pv    = (float2*)(smem + P_OFF);
    float*  ws2   = smem + W2S_OFF;
    float2* As2   = (float2*)(smem + AS2_OFF);
    float2* Xs    = (float2*)(smem + XS_OFF);
    float2* Yp    = (float2*)(smem + YP_OFF);
    float*  bias1 = smem + B1_OFF;
    float*  wijb  = smem + WIJB_OFF;

    for (int i = tid; i < 208 * 64; i += 256) ws2[i] = g_Wt2[i];
    for (int i = tid; i < 384; i += 256) {
        float b;
        if (i < 192) b = wr_b[i];
        else { int tt = i - 192, g = tt >> 6, u = tt & 63;
               b = wz_b[64 * (g + 1) + u] - wz_b[u]; }
        bias1[i] = b;
    }
    if (tid < 64) wijb[tid] = wij_b[tid];
    for (int i = tid; i < 7680; i += 256) smem[HE_OFF + i] = 0.0f;  // He,Ho,Ht
    {   // Xs for s=0: cell (2p, 0), padded rows
        const float2* Xp0 = g_Xp + ((size_t)((2 * p) * 64 + 0) * 4 + q) * 128;
        if (tid < 128) Xs[(tid >> 3) * RS + (tid & 7)] = Xp0[tid];
    }
    __syncthreads();

    const float* Wb  = g_Wt1 + (size_t)(kg * 52) * N1 + nl;
    const float* Wb2 = ws2 + (size_t)(kg * 52) * 64 + nl;

    for (int s = 0; s < 128; s++) {
        const int sub = s & 1;
        const int r = s >> 1;
        const int l = 2 * p + sub;
        const int rb = r & 1, rp = rb ^ 1;

        float2 *T, *Lf, *Dg, *hdst;
        if (sub == 0) {
            T  = (float2*)(smem + HT_OFF) + rb * (64 * RS);
            Lf = (float2*)(smem + HE_OFF) + rp * (64 * RS);
            Dg = (float2*)(smem + HT_OFF) + rp * (64 * RS);
            hdst = (float2*)(smem + HE_OFF) + rb * (64 * RS);
        } else {
            T  = (float2*)(smem + HE_OFF) + rb * (64 * RS);
            Lf = (float2*)(smem + HO_OFF) + rp * (64 * RS);
            Dg = (float2*)(smem + HE_OFF) + rp * (64 * RS);
            hdst = (float2*)(smem + HO_OFF) + rb * (64 * RS);
        }

        if (sub == 0 && p > 0) {
            if (tid == 0) {
                const int* fp = &g_flag[(q * 64 + (2 * p - 1)) * 64 + r];
                int v;
                do {
                    asm volatile("ld.acquire.gpu.global.b32 %0, [%1];" : "=r"(v) : "l"(fp));
                    if (!v) __nanosleep(64);
                } while (!v);
            }
            __syncthreads();
            const float2* Gt = (const float2*)(g_H + ((size_t)((2 * p - 1) * 64 + r)) * 4096 + q * 1024);
#pragma unroll
            for (int i = 0; i < 2; i++) {
                int f = tid + 256 * i;
                T[(f >> 3) * RS + (f & 7)] = Gt[f];
            }
            __syncthreads();
        }

        // ---- stage-1 GEMM: A = ring rows (+Xs), W1 from L2 ----
        float wbuf[4][JT];
#pragma unroll
        for (int t4 = 0; t4 < 4; t4++)
#pragma unroll
            for (int j = 0; j < JT; j++) wbuf[t4][j] = Wb[(size_t)t4 * N1 + 64 * j];

        ull acc[JT][8];
#pragma unroll
        for (int j = 0; j < JT; j++)
#pragma unroll
            for (int m = 0; m < 8; m++) acc[j][m] = 0ULL;

        if (kg == 0)      { SEG1(T,  52, 0) }
        else if (kg == 1) { SEG1(Lf, 52, 0) }
        else if (kg == 2) { SEG1(Dg, 52, 0) }
        else {
            SEG1(T + 52 * RS,  12, 0)
            SEG1(Lf + 52 * RS, 12, 12)
            SEG1(Dg + 52 * RS, 12, 24)
            SEG1(Xs,           16, 36)
        }
#pragma unroll
        for (int j = 0; j < JT; j++)
#pragma unroll
            for (int m = 0; m < 8; m++)
                Pv[(size_t)kg * 3072 + (j * 8 + m) * 64 + nl] = unpack2(acc[j][m]);
        __syncthreads();

        // ---- reduce1: rr -> As2 (rr*H), z-diff -> Yp ----
#pragma unroll
        for (int i = 0; i < 12; i++) {
            int f = tid + 256 * i;
            int nl2 = f & 63, m = (f >> 6) & 7, j = f >> 9;
            int base = (j * 8 + m) * 64 + nl2;
            float2 s0 = Pv[base], s1 = Pv[3072 + base];
            float2 s2 = Pv[6144 + base], s3 = Pv[9216 + base];
            int n = nl2 + 64 * j;
            float b = bias1[n];
            float x0 = ((s0.x + s1.x) + (s2.x + s3.x)) + b;
            float x1 = ((s0.y + s1.y) + (s2.y + s3.y)) + b;
            if (j < 3) {
                x0 = __fdividef(1.0f, 1.0f + __expf(-x0));
                x1 = __fdividef(1.0f, 1.0f + __expf(-x1));
                const float2* hsrc = (j == 0) ? Lf : ((j == 1) ? T : Dg);
                float2 hp = hsrc[nl2 * RS + m];
                As2[(size_t)n * RS + m] = make_float2(x0 * hp.x, x1 * hp.y);
            } else {
                Yp[(size_t)(j - 3) * (64 * RS) + nl2 * RS + m] = make_float2(x0, x1);
            }
        }
        __syncthreads();

        // ---- stage-2 GEMM: A = As2 (+Xs), W2 from smem ----
        float w2buf[4];
#pragma unroll
        for (int t4 = 0; t4 < 4; t4++) w2buf[t4] = Wb2[t4 * 64];
        ull acc2[8];
#pragma unroll
        for (int m = 0; m < 8; m++) acc2[m] = 0ULL;

        if (kg < 3) { SEG2(As2 + kg * 52 * RS, 52, 0) }
        else {
            SEG2(As2 + 156 * RS, 36, 0)
            SEG2(Xs,             16, 36)
        }
#pragma unroll
        for (int m = 0; m < 8; m++)
            Pv[(size_t)kg * 512 + m * 64 + nl] = unpack2(acc2[m]);
        __syncthreads();

        // ---- epilogue: reduce + tanh + gates + H update + Xs prefetch ----
        {
            float2* Gd = (float2*)(g_H + ((size_t)(l * 64 + r)) * 4096 + q * 1024);
            const bool last = (l == 63) && (r == 63);
#pragma unroll
            for (int i = 0; i < 2; i++) {
                int f = tid + 256 * i;
                int u = f & 63, m = f >> 6;
                int base = m * 64 + u;
                float2 s0 = Pv[base], s1 = Pv[512 + base];
                float2 s2 = Pv[1024 + base], s3 = Pv[1536 + base];
                float wb = wijb[u];
                float a0 = ((s0.x + s1.x) + (s2.x + s3.x)) + wb;
                float a1 = ((s0.y + s1.y) + (s2.y + s3.y)) + wb;
                float hn0 = fast_tanh(a0), hn1 = fast_tanh(a1);
                int pi = u * RS + m;
                float2 z1 = Yp[pi], z2 = Yp[64 * RS + pi], z3 = Yp[128 * RS + pi];
                float2 hl = Lf[pi], ht = T[pi], hd = Dg[pi];
                float mx0 = fmaxf(fmaxf(z1.x, z2.x), fmaxf(z3.x, 0.0f));
                float e00 = __expf(-mx0);
                float e10 = __expf(z1.x - mx0), e20 = __expf(z2.x - mx0), e30 = __expf(z3.x - mx0);
                float h0 = (e00 * hn0 + e10 * hl.x + e20 * ht.x + e30 * hd.x) *
                           __fdividef(1.0f, e00 + e10 + e20 + e30);
                float mx1 = fmaxf(fmaxf(z1.y, z2.y), fmaxf(z3.y, 0.0f));
                float e01 = __expf(-mx1);
                float e11 = __expf(z1.y - mx1), e21 = __expf(z2.y - mx1), e31 = __expf(z3.y - mx1);
                float h1 = (e01 * hn1 + e11 * hl.y + e21 * ht.y + e31 * hd.y) *
                           __fdividef(1.0f, e01 + e11 + e21 + e31);
                float2 h2 = make_float2(h0, h1);
                hdst[pi] = h2;
                if (sub == 1) Gd[u * 8 + m] = h2;
                if (last) { out[(b0 + 2 * m) * 64 + u] = h0;
                            out[(b0 + 2 * m + 1) * 64 + u] = h1; }
            }
            if (s < 127 && tid < 128) {
                int s2_ = s + 1;
                int r2 = s2_ >> 1, l2 = 2 * p + (s2_ & 1);
                const float2* Xpn = g_Xp + ((size_t)(l2 * 64 + r2) * 4 + q) * 128;
                Xs[(tid >> 3) * RS + (tid & 7)] = Xpn[tid];
            }
        }
        __syncthreads();

        if (sub == 1 && tid == 0) {
            __threadfence();
            int* fp = &g_flag[(q * 64 + l) * 64 + r];
            asm volatile("st.release.gpu.global.b32 [%0], %1;" :: "l"(fp), "r"(1) : "memory");
        }
    }
}

extern "C" void kernel_launch(void* const* d_in, const int* in_sizes, int n_in,
                              void* d_out, int out_size)
{
    const float* inputs = (const float*)d_in[0];
    const float* wr_w   = (const float*)d_in[1];
    const float* wr_b   = (const float*)d_in[2];
    const float* wz_w   = (const float*)d_in[3];
    const float* wz_b   = (const float*)d_in[4];
    const float* wij_w  = (const float*)d_in[5];
    const float* wij_b  = (const float*)d_in[6];
    const float* U_w    = (const float*)d_in[7];
    float* out = (float*)d_out;

    cudaFuncSetAttribute(pipeline_kernel, cudaFuncAttributeMaxDynamicSharedMemorySize, SMEM_BYTES);

    init_kernel<<<512, 256>>>(inputs, wr_w, wz_w, U_w, wij_w);
    pipeline_kernel<<<128, 256, SMEM_BYTES>>>(wr_b, wz_b, wij_b, out);
}

// round 9
// speedup vs baseline: 1.2475x; 1.1488x over previous
#include <cuda_runtime.h>
#include <math.h>

typedef unsigned long long ull;

// SpatialGRU B=64,C=16,L=R=64,U=64,K=208. Persistent row-pipelined kernel.
// Round-9 = Round-6 structure (best so far) + (a) W2 resident in smem,
// (b) build-A2 fused into reduce1 (one fewer phase+barrier), (c) x-columns
// of As prefetched during previous epilogue (shared by A1 and A2).

#define KDIM 208
#define N1   384
#define JT   6

// smem float offsets
#define P_OFF    0          // [4 kg][6 j][8 mp][64 nl] float2 = 24576 floats
#define W2S_OFF  24576      // 208*64 = 13312
#define AS_OFF   37888      // float2[208][8] = 3328 floats
#define HE_OFF   41216      // [2][16][64] = 2048
#define HO_OFF   43264      // 2048
#define HT_OFF   45312      // 2048
#define YP_OFF   47360      // [3][16][64] = 3072
#define B1_OFF   50432      // 384
#define WIJB_OFF 50816      // 64
#define SMEM_FLOATS 50880
#define SMEM_BYTES (SMEM_FLOATS*4)

__device__ float  g_H[64 * 64 * 64 * 64];  // [(l*64+r)][b][u]; only odd l used
__device__ float2 g_Xp[4096 * 4 * 128];    // [(l*64+r)][q][c][mp] m-paired x
__device__ float  g_Wt1[208 * 384];        // [k][n] n<192: wr ; n>=192: wz-diff
__device__ float  g_Wt2[208 * 64];         // [k][n] k<192: U_w ; else wij
__device__ int    g_flag[4 * 64 * 64];     // [q][row][r]

#define FMA2(acc, a, b) asm("fma.rn.f32x2 %0, %1, %2, %0;" : "+l"(acc) : "l"(a), "l"(b))

__device__ __forceinline__ ull dup2(float w) {
    unsigned int wi = __float_as_uint(w);
    ull d;
    asm("mov.b64 %0, {%1,%2};" : "=l"(d) : "r"(wi), "r"(wi));
    return d;
}
__device__ __forceinline__ float2 unpack2(ull v) {
    unsigned int a, b;
    asm("mov.b64 {%0,%1}, %2;" : "=r"(a), "=r"(b) : "l"(v));
    return make_float2(__uint_as_float(a), __uint_as_float(b));
}
__device__ __forceinline__ float fast_tanh(float x) {
    x = fminf(fmaxf(x, -15.0f), 15.0f);
    float e = __expf(2.0f * x);
    return __fdividef(e - 1.0f, e + 1.0f);
}

extern "C" __global__ void init_kernel(const float* __restrict__ inputs,
                                       const float* __restrict__ wr_w,
                                       const float* __restrict__ wz_w,
                                       const float* __restrict__ U_w,
                                       const float* __restrict__ wij_w)
{
    int t = blockIdx.x * blockDim.x + threadIdx.x;
    int stride = gridDim.x * blockDim.x;
    for (int i = t; i < 4 * 64 * 64; i += stride) g_flag[i] = 0;
    for (int i = t; i < 4096 * 4 * 128; i += stride) {
        int mp = i & 7, c = (i >> 3) & 15, q = (i >> 7) & 3, cell = i >> 9;
        int l = cell >> 6, r = cell & 63, b = q * 16 + 2 * mp;
        float v0 = inputs[((b * 16 + c) * 64 + l) * 64 + r];
        float v1 = inputs[(((b + 1) * 16 + c) * 64 + l) * 64 + r];
        g_Xp[i] = make_float2(v0, v1);
    }
    for (int i = t; i < 208 * 384; i += stride) {
        int k = i / 384, n = i - k * 384;
        float w;
        if (n < 192) w = wr_w[n * KDIM + k];
        else { int tt = n - 192, g = tt >> 6, u = tt & 63;
               w = wz_w[(64 * (g + 1) + u) * KDIM + k] - wz_w[u * KDIM + k]; }
        g_Wt1[i] = w;
    }
    for (int i = t; i < 208 * 64; i += stride) {
        int k = i >> 6, n = i & 63;
        g_Wt2[i] = (k < 192) ? U_w[n * 192 + k] : wij_w[n * 16 + (k - 192)];
    }
}

extern __shared__ float smem[];

#define LDW1(dst, KK) { const float* _b = wp + (size_t)(KK) * N1; \
    _Pragma("unroll") for (int _j = 0; _j < JT; _j++) dst[_j] = _b[_j * 64]; }
#define LDA(dst, KK) { const ulonglong2* _r = Ab + (KK) * 4; \
    dst[0] = _r[0]; dst[1] = _r[1]; dst[2] = _r[2]; dst[3] = _r[3]; }
#define FMAB(WD, A) { _Pragma("unroll") for (int _j = 0; _j < JT; _j++) { \
    FMA2(acc[_j][0], A[0].x, WD[_j]); FMA2(acc[_j][1], A[0].y, WD[_j]); \
    FMA2(acc[_j][2], A[1].x, WD[_j]); FMA2(acc[_j][3], A[1].y, WD[_j]); \
    FMA2(acc[_j][4], A[2].x, WD[_j]); FMA2(acc[_j][5], A[2].y, WD[_j]); \
    FMA2(acc[_j][6], A[3].x, WD[_j]); FMA2(acc[_j][7], A[3].y, WD[_j]); } }

extern "C" __global__ void __launch_bounds__(256, 1)
pipeline_kernel(const float* __restrict__ wr_b, const float* __restrict__ wz_b,
                const float* __restrict__ wij_b, float* __restrict__ out)
{
    const int tid = threadIdx.x;
    const int p = blockIdx.x >> 2;     // row pair 0..31
    const int q = blockIdx.x & 3;      // batch quarter
    const int b0 = q * 16;
    const int nl = tid & 63;           // n-lane
    const int kg = tid >> 6;           // k-group (52 k each)
    const int mp_b = tid >> 5;         // build-phase m-pair 0..7
    const int kb_b = tid & 31;

    float2* Pv    = (float2*)(smem + P_OFF);
    float*  ws2   = smem + W2S_OFF;
    float2* As    = (float2*)(smem + AS_OFF);
    float*  He    = smem + HE_OFF;
    float*  Ho    = smem + HO_OFF;
    float*  Ht    = smem + HT_OFF;
    float*  Yp    = smem + YP_OFF;
    float*  bias1 = smem + B1_OFF;
    float*  wijb  = smem + WIJB_OFF;

    // one-time preload
    for (int i = tid; i < 208 * 64; i += 256) ws2[i] = g_Wt2[i];
    for (int i = tid; i < 384; i += 256) {
        float b;
        if (i < 192) b = wr_b[i];
        else { int tt = i - 192, g = tt >> 6, u = tt & 63;
               b = wz_b[64 * (g + 1) + u] - wz_b[u]; }
        bias1[i] = b;
    }
    if (tid < 64) wijb[tid] = wij_b[tid];
    for (int i = tid; i < 6144; i += 256) He[i] = 0.0f;   // He,Ho,Ht contiguous
    {   // x-section of As for s=0: cell (2p, 0)
        const float2* Xp0 = g_Xp + ((size_t)((2 * p) * 64 + 0) * 4 + q) * 128;
        if (tid < 128) As[(192 + (tid >> 3)) * 8 + (tid & 7)] = Xp0[tid];
    }
    __syncthreads();

    const float* wp  = g_Wt1 + (size_t)(kg * 52) * N1 + nl;
    const float* Wb2 = ws2 + (size_t)(kg * 52) * 64 + nl;
    const ulonglong2* Ab = (const ulonglong2*)As + (size_t)(kg * 52) * 4;

    for (int s = 0; s < 128; s++) {
        const int sub = s & 1;
        const int r = s >> 1;
        const int l = 2 * p + sub;
        const int rb = r & 1, rp = rb ^ 1;

        const float *hl_s, *ht_s, *hd_s;
        float* hdst;
        if (sub == 0) { hl_s = He + rp * 1024; ht_s = Ht + rb * 1024;
                        hd_s = Ht + rp * 1024; hdst = He + rb * 1024; }
        else          { hl_s = Ho + rp * 1024; ht_s = He + rb * 1024;
                        hd_s = He + rp * 1024; hdst = Ho + rb * 1024; }

        if (sub == 0 && p > 0) {
            if (tid == 0) {
                const int* fp = &g_flag[(q * 64 + (2 * p - 1)) * 64 + r];
                int v;
                do {
                    asm volatile("ld.acquire.gpu.global.b32 %0, [%1];" : "=r"(v) : "l"(fp));
                    if (!v) __nanosleep(64);
                } while (!v);
            }
            __syncthreads();
        }

        const float* Gtop = g_H + ((size_t)((2 * p - 1) * 64 + r)) * 4096 + b0 * 64;
        float* Htcur = Ht + rb * 1024;

        // ---- build A1 h-sections [k<192][mp] = m-paired {h_top|h_left|h_diag} ----
        {
            const int m0 = 2 * mp_b, m1 = m0 + 1;
#pragma unroll
            for (int c = 0; c < 6; c++) {
                int k = kb_b + 32 * c;
                float v0, v1;
                if (k < 64) {
                    if (sub == 0) {
                        if (p > 0) {
                            v0 = Gtop[m0 * 64 + k]; v1 = Gtop[m1 * 64 + k];
                            Htcur[m0 * 64 + k] = v0; Htcur[m1 * 64 + k] = v1;
                        } else { v0 = 0.0f; v1 = 0.0f; }
                    } else {
                        v0 = ht_s[m0 * 64 + k]; v1 = ht_s[m1 * 64 + k];
                    }
                } else if (k < 128) {
                    int ko = k - 64;
                    v0 = hl_s[m0 * 64 + ko]; v1 = hl_s[m1 * 64 + ko];
                } else {
                    int ko = k - 128;
                    v0 = hd_s[m0 * 64 + ko]; v1 = hd_s[m1 * 64 + ko];
                }
                As[k * 8 + mp_b] = make_float2(v0, v1);
            }
        }
        // hoisted stage-1 W prologue
        float wA[JT], wB[JT];
        LDW1(wA, 0); LDW1(wB, 1);
        __syncthreads();

        // ---- stage-1 GEMM: acc[j][mp], W from L2 (4-deep), A broadcast ----
        ull acc[JT][8];
#pragma unroll
        for (int j = 0; j < JT; j++)
#pragma unroll
            for (int m = 0; m < 8; m++) acc[j][m] = 0ULL;
        {
            ulonglong2 aA[4], aB[4];
            LDA(aA, 0);
            for (int kk = 0; kk < 52; kk += 2) {
                ull wdA[JT];
#pragma unroll
                for (int j = 0; j < JT; j++) wdA[j] = dup2(wA[j]);
                LDA(aB, kk + 1);
                if (kk + 2 < 52) LDW1(wA, kk + 2);
                FMAB(wdA, aA);
                ull wdB[JT];
#pragma unroll
                for (int j = 0; j < JT; j++) wdB[j] = dup2(wB[j]);
                if (kk + 2 < 52) LDA(aA, kk + 2);
                if (kk + 3 < 52) LDW1(wB, kk + 3);
                FMAB(wdB, aB);
            }
        }
#pragma unroll
        for (int j = 0; j < JT; j++)
#pragma unroll
            for (int m = 0; m < 8; m++)
                Pv[(size_t)kg * 3072 + (j * 8 + m) * 64 + nl] = unpack2(acc[j][m]);
        __syncthreads();

        // ---- reduce1 (fused build-A2): rr -> As = rr*hu ; z-diff -> Yp ----
#pragma unroll
        for (int i = 0; i < 12; i++) {
            int f = tid + 256 * i;
            int nl2 = f & 63, m = (f >> 6) & 7, j = f >> 9;
            int base = (j * 8 + m) * 64 + nl2;
            float2 s0 = Pv[base], s1 = Pv[3072 + base];
            float2 s2 = Pv[6144 + base], s3 = Pv[9216 + base];
            int n = nl2 + 64 * j;
            float b = bias1[n];
            float x0 = ((s0.x + s1.x) + (s2.x + s3.x)) + b;
            float x1 = ((s0.y + s1.y) + (s2.y + s3.y)) + b;
            if (j < 3) {
                x0 = __fdividef(1.0f, 1.0f + __expf(-x0));
                x1 = __fdividef(1.0f, 1.0f + __expf(-x1));
                // A2 k-order: [h_left | h_top | h_diag]
                const float* Hs = (j == 0) ? hl_s : ((j == 1) ? ht_s : hd_s);
                float h0 = Hs[(2 * m) * 64 + nl2];
                float h1 = Hs[(2 * m + 1) * 64 + nl2];
                As[n * 8 + m] = make_float2(x0 * h0, x1 * h1);
            } else {
                int g = j - 3;
                Yp[g * 1024 + (2 * m) * 64 + nl2] = x0;
                Yp[g * 1024 + (2 * m + 1) * 64 + nl2] = x1;
            }
        }
        // hoisted stage-2 W prologue (smem)
        float w4[4];
#pragma unroll
        for (int i = 0; i < 4; i++) w4[i] = Wb2[i * 64];
        __syncthreads();

        // ---- stage-2 GEMM: A = As, W2 from smem ----
        ull acc2[8];
#pragma unroll
        for (int m = 0; m < 8; m++) acc2[m] = 0ULL;
        {
#pragma unroll 4
            for (int kk = 0; kk < 52; kk++) {
                ulonglong2 a[4];
                LDA(a, kk);
                ull wd = dup2(w4[kk & 3]);
                if (kk + 4 < 52) w4[kk & 3] = Wb2[(kk + 4) * 64];
                FMA2(acc2[0], a[0].x, wd); FMA2(acc2[1], a[0].y, wd);
                FMA2(acc2[2], a[1].x, wd); FMA2(acc2[3], a[1].y, wd);
                FMA2(acc2[4], a[2].x, wd); FMA2(acc2[5], a[2].y, wd);
                FMA2(acc2[6], a[3].x, wd); FMA2(acc2[7], a[3].y, wd);
            }
        }
#pragma unroll
        for (int m = 0; m < 8; m++)
            Pv[(size_t)kg * 512 + m * 64 + nl] = unpack2(acc2[m]);
        __syncthreads();

        // ---- epilogue: reduce + tanh + gates + H update + x prefetch ----
        {
            float* Gout = g_H + ((size_t)(l * 64 + r)) * 4096 + b0 * 64;
            const bool last = (l == 63) && (r == 63);
#pragma unroll
            for (int i = 0; i < 2; i++) {
                int f = tid + 256 * i;
                int u = f & 63, m = f >> 6;
                int base = m * 64 + u;
                float2 s0 = Pv[base], s1 = Pv[512 + base];
                float2 s2 = Pv[1024 + base], s3 = Pv[1536 + base];
                float wb = wijb[u];
                float av[2] = {((s0.x + s1.x) + (s2.x + s3.x)) + wb,
                               ((s0.y + s1.y) + (s2.y + s3.y)) + wb};
#pragma unroll
                for (int h2 = 0; h2 < 2; h2++) {
                    int mm = 2 * m + h2;
                    float hnew = fast_tanh(av[h2]);
                    float z1 = Yp[mm * 64 + u];
                    float z2 = Yp[1024 + mm * 64 + u];
                    float z3 = Yp[2048 + mm * 64 + u];
                    float mx = fmaxf(fmaxf(z1, z2), fmaxf(z3, 0.0f));
                    float e0 = __expf(-mx);
                    float e1 = __expf(z1 - mx), e2 = __expf(z2 - mx), e3 = __expf(z3 - mx);
                    float inv = __fdividef(1.0f, e0 + e1 + e2 + e3);
                    float h = (e0 * hnew + e1 * hl_s[mm * 64 + u] +
                               e2 * ht_s[mm * 64 + u] + e3 * hd_s[mm * 64 + u]) * inv;
                    hdst[mm * 64 + u] = h;
                    if (sub == 1) Gout[mm * 64 + u] = h;
                    if (last) out[(b0 + mm) * 64 + u] = h;
                }
            }
            if (s < 127 && tid < 128) {   // x-section of As for next cell
                int s2_ = s + 1;
                int r2 = s2_ >> 1, l2 = 2 * p + (s2_ & 1);
                const float2* Xpn = g_Xp + ((size_t)(l2 * 64 + r2) * 4 + q) * 128;
                As[(192 + (tid >> 3)) * 8 + (tid & 7)] = Xpn[tid];
            }
        }
        __syncthreads();

        if (sub == 1 && tid == 0) {
            __threadfence();
            int* fp = &g_flag[(q * 64 + l) * 64 + r];
            asm volatile("st.release.gpu.global.b32 [%0], %1;" :: "l"(fp), "r"(1) : "memory");
        }
    }
}

extern "C" void kernel_launch(void* const* d_in, const int* in_sizes, int n_in,
                              void* d_out, int out_size)
{
    const float* inputs = (const float*)d_in[0];
    const float* wr_w   = (const float*)d_in[1];
    const float* wr_b   = (const float*)d_in[2];
    const float* wz_w   = (const float*)d_in[3];
    const float* wz_b   = (const float*)d_in[4];
    const float* wij_w  = (const float*)d_in[5];
    const float* wij_b  = (const float*)d_in[6];
    const float* U_w    = (const float*)d_in[7];
    float* out = (float*)d_out;

    cudaFuncSetAttribute(pipeline_kernel, cudaFuncAttributeMaxDynamicSharedMemorySize, SMEM_BYTES);

    init_kernel<<<512, 256>>>(inputs, wr_w, wz_w, U_w, wij_w);
    pipeline_kernel<<<128, 256, SMEM_BYTES>>>(wr_b, wz_b, wij_b, out);
}